// round 2
// baseline (speedup 1.0000x reference)
#include <cuda_runtime.h>

#define NN 50000
#define NE 800000
#define DIM 128
#define NG 64

// ---------------- static device scratch (no allocations allowed) -------------
static __device__ float g_agg[NN * DIM];   // mean-aggregated features
static __device__ float g_hA [NN * DIM];   // layer output ping
static __device__ float g_hB [NN * DIM];   // layer output pong
static __device__ int   g_deg[NN];
static __device__ int   g_rowstart[NN];
static __device__ int   g_cursor[NN];
static __device__ float g_invdeg[NN];
static __device__ int   g_csr[NE];
static __device__ int   g_gcnt[NG];

// ---------------- CSR build -------------------------------------------------
__global__ void k_zero() {
    int i = blockIdx.x * blockDim.x + threadIdx.x;
    if (i < NN) g_deg[i] = 0;
    if (i < NG) g_gcnt[i] = 0;
}

__global__ void k_count_edges(const int* __restrict__ ei) {
    int e = blockIdx.x * blockDim.x + threadIdx.x;
    if (e < NE) {
        int d = ei[NE + e];
        atomicAdd(&g_deg[d], 1);
    }
}

__global__ void k_count_nodes(const int* __restrict__ batch) {
    int i = blockIdx.x * blockDim.x + threadIdx.x;
    if (i < NN) atomicAdd(&g_gcnt[batch[i]], 1);
}

// single-block scan of degrees -> rowstart/cursor/invdeg
__global__ void k_scan() {
    __shared__ int part[1024];
    const int T = 1024;
    const int C = (NN + T - 1) / T;   // 49
    int t = threadIdx.x;
    int base = t * C;
    int s = 0;
    for (int j = 0; j < C; j++) {
        int i = base + j;
        if (i < NN) s += g_deg[i];
    }
    part[t] = s;
    __syncthreads();
    for (int off = 1; off < T; off <<= 1) {
        int v = (t >= off) ? part[t - off] : 0;
        __syncthreads();
        part[t] += v;
        __syncthreads();
    }
    int run = (t > 0) ? part[t - 1] : 0;   // exclusive prefix
    for (int j = 0; j < C; j++) {
        int i = base + j;
        if (i < NN) {
            int d = g_deg[i];
            g_rowstart[i] = run;
            g_cursor[i]   = run;
            g_invdeg[i]   = (d > 0) ? 1.0f / (float)d : 0.0f;
            run += d;
        }
    }
}

__global__ void k_fill(const int* __restrict__ ei) {
    int e = blockIdx.x * blockDim.x + threadIdx.x;
    if (e >= NE) return;
    int s = ei[e];
    int d = ei[NE + e];
    int pos = atomicAdd(&g_cursor[d], 1);
    g_csr[pos] = s;
}

// ---------------- mean aggregation (warp per node, float4 lanes) ------------
__global__ void k_agg(const float* __restrict__ x, int sel) {
    const float* hin = (sel == 0) ? x : ((sel == 1) ? g_hA : g_hB);
    int gw   = (blockIdx.x * blockDim.x + threadIdx.x) >> 5;
    int lane = threadIdx.x & 31;
    if (gw >= NN) return;
    int start = g_rowstart[gw];
    int d     = g_deg[gw];
    const float4* x4 = (const float4*)hin;
    float a0 = 0.f, a1 = 0.f, a2 = 0.f, a3 = 0.f;
    for (int j = 0; j < d; j++) {
        int sidx = g_csr[start + j];
        float4 v = x4[sidx * 32 + lane];
        a0 += v.x; a1 += v.y; a2 += v.z; a3 += v.w;
    }
    float inv = g_invdeg[gw];
    float4 o;
    o.x = a0 * inv; o.y = a1 * inv; o.z = a2 * inv; o.w = a3 * inv;
    ((float4*)g_agg)[gw * 32 + lane] = o;
}

// ---------------- fused SAGE linear: out = agg@Wl^T + h@Wr^T + b ------------
// block tile: 32 nodes x 128 cols, 256 threads, 4x4 register tile per thread
__global__ void __launch_bounds__(256) k_gemm(
    const float* __restrict__ x, int sel_in, int sel_out,
    const float* __restrict__ Wl, const float* __restrict__ bl,
    const float* __restrict__ Wr, int relu)
{
    const float* hin  = (sel_in == 0) ? x : ((sel_in == 1) ? g_hA : g_hB);
    float*       hout = (sel_out == 1) ? g_hA : g_hB;

    __shared__ float As[32][16];    // node-major, broadcast reads
    __shared__ float Ws[16][128];   // k-major, float4 reads

    int tid = threadIdx.x;
    int cg  = tid & 31;     // col group: cols cg*4 .. cg*4+3
    int ng  = tid >> 5;     // node group: nodes ng*4 .. ng*4+3
    int nb  = blockIdx.x * 32;

    int wc  = tid >> 1;          // 0..127  (W load: column index)
    int wk0 = (tid & 1) * 8;     // 0 or 8  (W load: k sub-range)

    float acc[4][4];
#pragma unroll
    for (int i = 0; i < 4; i++)
#pragma unroll
        for (int j = 0; j < 4; j++) acc[i][j] = 0.f;

    for (int kb = 0; kb < 256; kb += 16) {
        // ---- load A tile (32 nodes x 16 k), k<128 -> agg, else hin ----
#pragma unroll
        for (int r = 0; r < 2; r++) {
            int e  = tid + r * 256;
            int n  = e >> 4;
            int kk = e & 15;
            int node = nb + n;
            int k    = kb + kk;
            float v = 0.f;
            if (node < NN)
                v = (k < 128) ? g_agg[node * 128 + k]
                              : hin[node * 128 + (k - 128)];
            As[n][kk] = v;
        }
        // ---- load W tile (16 k x 128 cols) ----
#pragma unroll
        for (int i = 0; i < 8; i++) {
            int kk = wk0 + i;
            int k  = kb + kk;
            float w = (k < 128) ? Wl[wc * 128 + k]
                                : Wr[wc * 128 + (k - 128)];
            Ws[kk][wc] = w;
        }
        __syncthreads();
#pragma unroll
        for (int kk = 0; kk < 16; kk++) {
            float4 w = *(const float4*)&Ws[kk][cg * 4];
            float a0 = As[ng * 4 + 0][kk];
            float a1 = As[ng * 4 + 1][kk];
            float a2 = As[ng * 4 + 2][kk];
            float a3 = As[ng * 4 + 3][kk];
            acc[0][0] += a0 * w.x; acc[0][1] += a0 * w.y; acc[0][2] += a0 * w.z; acc[0][3] += a0 * w.w;
            acc[1][0] += a1 * w.x; acc[1][1] += a1 * w.y; acc[1][2] += a1 * w.z; acc[1][3] += a1 * w.w;
            acc[2][0] += a2 * w.x; acc[2][1] += a2 * w.y; acc[2][2] += a2 * w.z; acc[2][3] += a2 * w.w;
            acc[3][0] += a3 * w.x; acc[3][1] += a3 * w.y; acc[3][2] += a3 * w.z; acc[3][3] += a3 * w.w;
        }
        __syncthreads();
    }

    float b0 = bl[cg * 4 + 0];
    float b1 = bl[cg * 4 + 1];
    float b2 = bl[cg * 4 + 2];
    float b3 = bl[cg * 4 + 3];
#pragma unroll
    for (int ni = 0; ni < 4; ni++) {
        int node = nb + ng * 4 + ni;
        if (node < NN) {
            float4 o;
            o.x = acc[ni][0] + b0;
            o.y = acc[ni][1] + b1;
            o.z = acc[ni][2] + b2;
            o.w = acc[ni][3] + b3;
            if (relu) {
                o.x = fmaxf(o.x, 0.f); o.y = fmaxf(o.y, 0.f);
                o.z = fmaxf(o.z, 0.f); o.w = fmaxf(o.w, 0.f);
            }
            ((float4*)hout)[node * 32 + cg] = o;
        }
    }
}

// ---------------- global mean pool (batch is sorted) ------------------------
__global__ void k_pool(float* __restrict__ out) {
    int g = blockIdx.x;
    int c = threadIdx.x;   // 128 threads = 128 cols
    int start = 0;
    for (int i = 0; i < g; i++) start += g_gcnt[i];
    int cnt = g_gcnt[g];
    float s = 0.f;
    for (int r = 0; r < cnt; r++)
        s += g_hA[(start + r) * 128 + c];
    out[g * 128 + c] = (cnt > 0) ? s / (float)cnt : 0.0f;
}

// ---------------- launch ----------------------------------------------------
extern "C" void kernel_launch(void* const* d_in, const int* in_sizes, int n_in,
                              void* d_out, int out_size)
{
    const float* x     = (const float*)d_in[0];
    const int*   ei    = (const int*)d_in[1];    // int64 in reference -> int32 here
    const int*   batch = (const int*)d_in[2];    // int64 in reference -> int32 here
    const float* Wl0 = (const float*)d_in[3];
    const float* bl0 = (const float*)d_in[4];
    const float* Wr0 = (const float*)d_in[5];
    const float* Wl1 = (const float*)d_in[6];
    const float* bl1 = (const float*)d_in[7];
    const float* Wr1 = (const float*)d_in[8];
    const float* Wl2 = (const float*)d_in[9];
    const float* bl2 = (const float*)d_in[10];
    const float* Wr2 = (const float*)d_in[11];
    float* out = (float*)d_out;

    // CSR build (per launch; deterministic values, atomic order may vary)
    k_zero<<<(NN + 255) / 256, 256>>>();
    k_count_edges<<<(NE + 255) / 256, 256>>>(ei);
    k_count_nodes<<<(NN + 255) / 256, 256>>>(batch);
    k_scan<<<1, 1024>>>();
    k_fill<<<(NE + 255) / 256, 256>>>(ei);

    int agg_blocks  = (NN * 32 + 255) / 256;   // warp per node
    int gemm_blocks = (NN + 31) / 32;

    // layer 0: x -> hA
    k_agg <<<agg_blocks, 256>>>(x, 0);
    k_gemm<<<gemm_blocks, 256>>>(x, 0, 1, Wl0, bl0, Wr0, 1);
    // layer 1: hA -> hB
    k_agg <<<agg_blocks, 256>>>(x, 1);
    k_gemm<<<gemm_blocks, 256>>>(x, 1, 2, Wl1, bl1, Wr1, 1);
    // layer 2: hB -> hA (no relu)
    k_agg <<<agg_blocks, 256>>>(x, 2);
    k_gemm<<<gemm_blocks, 256>>>(x, 2, 1, Wl2, bl2, Wr2, 0);
    // pool
    k_pool<<<NG, 128>>>(out);
}

// round 3
// speedup vs baseline: 1.8933x; 1.8933x over previous
#include <cuda_runtime.h>

#define NN 50000
#define NE 800000
#define DIM 128
#define NG 64
#define SCAN_B 256
#define NBLK ((NN + SCAN_B - 1) / SCAN_B)   // 196

// ---------------- static device scratch -------------------------------------
static __device__ float g_agg[NN * DIM];
static __device__ float g_hA [NN * DIM];
static __device__ float g_hB [NN * DIM];
static __device__ int   g_deg[NN];
static __device__ int   g_rowstart[NN];
static __device__ int   g_cursor[NN];
static __device__ float g_invdeg[NN];
static __device__ int   g_csr[NE];
static __device__ int   g_gcnt[NG];
static __device__ int   g_bsum[NBLK];
static __device__ int   g_boff[NBLK];

// ---------------- init + counts ---------------------------------------------
__global__ void k_zero() {
    int i = blockIdx.x * blockDim.x + threadIdx.x;
    if (i < NN) g_deg[i] = 0;
    if (i < NG) g_gcnt[i] = 0;
}

__global__ void k_count(const int* __restrict__ ei, const int* __restrict__ batch) {
    int e = blockIdx.x * blockDim.x + threadIdx.x;
    if (e < NE) atomicAdd(&g_deg[ei[NE + e]], 1);
    if (e < NN) atomicAdd(&g_gcnt[batch[e]], 1);
}

// ---------------- hierarchical scan of degrees ------------------------------
__global__ void k_blocksum() {
    __shared__ int wsum[8];
    int i = blockIdx.x * SCAN_B + threadIdx.x;
    int v = (i < NN) ? g_deg[i] : 0;
    int s = v;
#pragma unroll
    for (int o = 16; o > 0; o >>= 1) s += __shfl_down_sync(0xffffffffu, s, o);
    if ((threadIdx.x & 31) == 0) wsum[threadIdx.x >> 5] = s;
    __syncthreads();
    if (threadIdx.x == 0) {
        int t = 0;
#pragma unroll
        for (int w = 0; w < 8; w++) t += wsum[w];
        g_bsum[blockIdx.x] = t;
    }
}

__global__ void k_scan2() {
    __shared__ int sh[SCAN_B];
    int t = threadIdx.x;
    sh[t] = (t < NBLK) ? g_bsum[t] : 0;
    __syncthreads();
#pragma unroll
    for (int off = 1; off < SCAN_B; off <<= 1) {
        int v = (t >= off) ? sh[t - off] : 0;
        __syncthreads();
        sh[t] += v;
        __syncthreads();
    }
    if (t < NBLK) g_boff[t] = (t > 0) ? sh[t - 1] : 0;   // exclusive
}

__global__ void k_apply() {
    __shared__ int wsum[8];
    int lane = threadIdx.x & 31;
    int wid  = threadIdx.x >> 5;
    int i = blockIdx.x * SCAN_B + threadIdx.x;
    int v = (i < NN) ? g_deg[i] : 0;
    // warp inclusive scan
    int inc = v;
#pragma unroll
    for (int o = 1; o < 32; o <<= 1) {
        int u = __shfl_up_sync(0xffffffffu, inc, o);
        if (lane >= o) inc += u;
    }
    if (lane == 31) wsum[wid] = inc;
    __syncthreads();
    if (wid == 0) {
        int ws = (lane < 8) ? wsum[lane] : 0;
#pragma unroll
        for (int o = 1; o < 8; o <<= 1) {
            int u = __shfl_up_sync(0xffffffffu, ws, o);
            if (lane >= o) ws += u;
        }
        if (lane < 8) wsum[lane] = ws;   // inclusive warp sums
    }
    __syncthreads();
    int excl = inc - v + ((wid > 0) ? wsum[wid - 1] : 0) + g_boff[blockIdx.x];
    if (i < NN) {
        g_rowstart[i] = excl;
        g_cursor[i]   = excl;
        g_invdeg[i]   = (v > 0) ? 1.0f / (float)v : 0.0f;
    }
}

__global__ void k_fill(const int* __restrict__ ei) {
    int e = blockIdx.x * blockDim.x + threadIdx.x;
    if (e >= NE) return;
    int s = ei[e];
    int d = ei[NE + e];
    int pos = atomicAdd(&g_cursor[d], 1);
    g_csr[pos] = s;
}

// ---------------- mean aggregation (warp per node) --------------------------
__global__ void k_agg(const float* __restrict__ x, int sel) {
    const float* hin = (sel == 0) ? x : ((sel == 1) ? g_hA : g_hB);
    int gw   = (blockIdx.x * blockDim.x + threadIdx.x) >> 5;
    int lane = threadIdx.x & 31;
    if (gw >= NN) return;
    int start = g_rowstart[gw];
    int d     = g_deg[gw];
    const float4* x4 = (const float4*)hin;
    float a0 = 0.f, a1 = 0.f, a2 = 0.f, a3 = 0.f;
    int j = 0;
    for (; j + 4 <= d; j += 4) {
        int s0 = g_csr[start + j + 0];
        int s1 = g_csr[start + j + 1];
        int s2 = g_csr[start + j + 2];
        int s3 = g_csr[start + j + 3];
        float4 v0 = x4[s0 * 32 + lane];
        float4 v1 = x4[s1 * 32 + lane];
        float4 v2 = x4[s2 * 32 + lane];
        float4 v3 = x4[s3 * 32 + lane];
        a0 += v0.x + v1.x + v2.x + v3.x;
        a1 += v0.y + v1.y + v2.y + v3.y;
        a2 += v0.z + v1.z + v2.z + v3.z;
        a3 += v0.w + v1.w + v2.w + v3.w;
    }
    for (; j < d; j++) {
        int s0 = g_csr[start + j];
        float4 v = x4[s0 * 32 + lane];
        a0 += v.x; a1 += v.y; a2 += v.z; a3 += v.w;
    }
    float inv = g_invdeg[gw];
    float4 o;
    o.x = a0 * inv; o.y = a1 * inv; o.z = a2 * inv; o.w = a3 * inv;
    ((float4*)g_agg)[gw * 32 + lane] = o;
}

// ---------------- fused SAGE linear: out = agg@Wl^T + h@Wr^T + b ------------
// 64 nodes x 128 cols, 256 threads, 8x4 register tile, transposed-A smem
__global__ void __launch_bounds__(256) k_gemm(
    const float* __restrict__ x, int sel_in, int sel_out,
    const float* __restrict__ Wl, const float* __restrict__ bl,
    const float* __restrict__ Wr, int relu)
{
    const float* hin  = (sel_in == 0) ? x : ((sel_in == 1) ? g_hA : g_hB);
    float*       hout = (sel_out == 1) ? g_hA : g_hB;

    __shared__ float As[16][68];    // [k][node], padded
    __shared__ float Ws[16][128];   // [k][col]

    int tid = threadIdx.x;
    int cg  = tid & 31;     // cols cg*4 .. cg*4+3
    int ng  = tid >> 5;     // nodes ng*8 .. ng*8+7
    int nb  = blockIdx.x * 64;

    // A load mapping: one float4 per thread: node an, k-quad aq
    int an = tid >> 2;          // 0..63
    int aq = tid & 3;           // kk = aq*4..aq*4+3
    // W load mapping: 2 float4 per thread over 512 quads
    float acc[8][4];
#pragma unroll
    for (int i = 0; i < 8; i++)
#pragma unroll
        for (int j = 0; j < 4; j++) acc[i][j] = 0.f;

    for (int kb = 0; kb < 256; kb += 16) {
        // ---- A tile: k<128 -> g_agg, else hin ----
        {
            int node = nb + an;
            float4 v = make_float4(0.f, 0.f, 0.f, 0.f);
            if (node < NN) {
                int k = kb + aq * 4;
                v = (k < 128) ? *(const float4*)&g_agg[node * 128 + k]
                              : *(const float4*)&hin[node * 128 + (k - 128)];
            }
            As[aq * 4 + 0][an] = v.x;
            As[aq * 4 + 1][an] = v.y;
            As[aq * 4 + 2][an] = v.z;
            As[aq * 4 + 3][an] = v.w;
        }
        // ---- W tile: k<128 -> Wl, else Wr ----
#pragma unroll
        for (int r = 0; r < 2; r++) {
            int f = tid + r * 256;   // quad index 0..511
            int c = f >> 2;          // col 0..127
            int q = f & 3;
            int k = kb + q * 4;
            float4 w = (k < 128) ? *(const float4*)&Wl[c * 128 + k]
                                 : *(const float4*)&Wr[c * 128 + (k - 128)];
            Ws[q * 4 + 0][c] = w.x;
            Ws[q * 4 + 1][c] = w.y;
            Ws[q * 4 + 2][c] = w.z;
            Ws[q * 4 + 3][c] = w.w;
        }
        __syncthreads();
#pragma unroll
        for (int kk = 0; kk < 16; kk++) {
            float4 w  = *(const float4*)&Ws[kk][cg * 4];
            float4 al = *(const float4*)&As[kk][ng * 8];
            float4 ah = *(const float4*)&As[kk][ng * 8 + 4];
            float a[8] = {al.x, al.y, al.z, al.w, ah.x, ah.y, ah.z, ah.w};
#pragma unroll
            for (int i = 0; i < 8; i++) {
                acc[i][0] += a[i] * w.x;
                acc[i][1] += a[i] * w.y;
                acc[i][2] += a[i] * w.z;
                acc[i][3] += a[i] * w.w;
            }
        }
        __syncthreads();
    }

    float b0 = bl[cg * 4 + 0];
    float b1 = bl[cg * 4 + 1];
    float b2 = bl[cg * 4 + 2];
    float b3 = bl[cg * 4 + 3];
#pragma unroll
    for (int ni = 0; ni < 8; ni++) {
        int node = nb + ng * 8 + ni;
        if (node < NN) {
            float4 o;
            o.x = acc[ni][0] + b0;
            o.y = acc[ni][1] + b1;
            o.z = acc[ni][2] + b2;
            o.w = acc[ni][3] + b3;
            if (relu) {
                o.x = fmaxf(o.x, 0.f); o.y = fmaxf(o.y, 0.f);
                o.z = fmaxf(o.z, 0.f); o.w = fmaxf(o.w, 0.f);
            }
            ((float4*)hout)[node * 32 + cg] = o;
        }
    }
}

// ---------------- global mean pool ------------------------------------------
__global__ void k_pool(float* __restrict__ out) {
    int g = blockIdx.x;
    int c = threadIdx.x;
    int start = 0;
    for (int i = 0; i < g; i++) start += g_gcnt[i];
    int cnt = g_gcnt[g];
    float s = 0.f;
    for (int r = 0; r < cnt; r++)
        s += g_hA[(start + r) * 128 + c];
    out[g * 128 + c] = (cnt > 0) ? s / (float)cnt : 0.0f;
}

// ---------------- launch ----------------------------------------------------
extern "C" void kernel_launch(void* const* d_in, const int* in_sizes, int n_in,
                              void* d_out, int out_size)
{
    const float* x     = (const float*)d_in[0];
    const int*   ei    = (const int*)d_in[1];
    const int*   batch = (const int*)d_in[2];
    const float* Wl0 = (const float*)d_in[3];
    const float* bl0 = (const float*)d_in[4];
    const float* Wr0 = (const float*)d_in[5];
    const float* Wl1 = (const float*)d_in[6];
    const float* bl1 = (const float*)d_in[7];
    const float* Wr1 = (const float*)d_in[8];
    const float* Wl2 = (const float*)d_in[9];
    const float* bl2 = (const float*)d_in[10];
    const float* Wr2 = (const float*)d_in[11];
    float* out = (float*)d_out;

    k_zero<<<(NN + 255) / 256, 256>>>();
    k_count<<<(NE + 255) / 256, 256>>>(ei, batch);
    k_blocksum<<<NBLK, SCAN_B>>>();
    k_scan2<<<1, SCAN_B>>>();
    k_apply<<<NBLK, SCAN_B>>>();
    k_fill<<<(NE + 255) / 256, 256>>>(ei);

    int agg_blocks  = (NN * 32 + 255) / 256;
    int gemm_blocks = (NN + 63) / 64;

    k_agg <<<agg_blocks, 256>>>(x, 0);
    k_gemm<<<gemm_blocks, 256>>>(x, 0, 1, Wl0, bl0, Wr0, 1);
    k_agg <<<agg_blocks, 256>>>(x, 1);
    k_gemm<<<gemm_blocks, 256>>>(x, 1, 2, Wl1, bl1, Wr1, 1);
    k_agg <<<agg_blocks, 256>>>(x, 2);
    k_gemm<<<gemm_blocks, 256>>>(x, 2, 1, Wl2, bl2, Wr2, 0);
    k_pool<<<NG, 128>>>(out);
}

// round 7
// speedup vs baseline: 2.5335x; 1.3381x over previous
#include <cuda_runtime.h>
#include <cuda_bf16.h>
#include <cstdint>

#define NN 50000
#define NE 800000
#define DIM 128
#define NG 64
#define SCAN_B 256
#define NBLK ((NN + SCAN_B - 1) / SCAN_B)   // 196

// ---------------- static device scratch -------------------------------------
static __device__ float    g_hA [NN * DIM];       // fp32 layer outputs (ping)
static __device__ float    g_hB [NN * DIM];       // fp32 layer outputs (pong)
static __device__ uint16_t g_aggh[NN * DIM];      // bf16 hi of mean-agg
static __device__ uint16_t g_aggl[NN * DIM];      // bf16 lo
static __device__ uint16_t g_xh[NN * DIM];        // bf16 hi of x
static __device__ uint16_t g_xl[NN * DIM];
static __device__ uint16_t g_hh0[NN * DIM];       // bf16 hi of h (layer0 out)
static __device__ uint16_t g_hl0[NN * DIM];
static __device__ uint16_t g_hh1[NN * DIM];       // bf16 hi of h (layer1 out)
static __device__ uint16_t g_hl1[NN * DIM];
static __device__ uint16_t g_Wbh[6 * 16384];      // bf16 hi of Wl0,Wr0,Wl1,Wr1,Wl2,Wr2
static __device__ uint16_t g_Wbl[6 * 16384];
static __device__ int   g_deg[NN];
static __device__ int   g_rowstart[NN];
static __device__ int   g_cursor[NN];
static __device__ float g_invdeg[NN];
static __device__ int   g_csr[NE];
static __device__ int   g_gcnt[NG];
static __device__ int   g_bsum[NBLK];
static __device__ int   g_boff[NBLK];

// ---------------- helpers ----------------------------------------------------
__device__ __forceinline__ uint32_t smem_u32(const void* p) {
    uint32_t a;
    asm("{ .reg .u64 t; cvta.to.shared.u64 t, %1; cvt.u32.u64 %0, t; }"
        : "=r"(a) : "l"(p));
    return a;
}

__device__ __forceinline__ void bf16_split(float v, uint16_t& h, uint16_t& l) {
    __nv_bfloat16 hb = __float2bfloat16(v);
    float hf = __bfloat162float(hb);
    __nv_bfloat16 lb = __float2bfloat16(v - hf);
    h = __bfloat16_as_ushort(hb);
    l = __bfloat16_as_ushort(lb);
}

#define LDSM_X4(r, addr) \
    asm volatile("ldmatrix.sync.aligned.m8n8.x4.shared.b16 {%0,%1,%2,%3}, [%4];" \
        : "=r"((r)[0]), "=r"((r)[1]), "=r"((r)[2]), "=r"((r)[3]) : "r"(addr))

#define MMA_BF16(d, a, b0v, b1v) \
    asm volatile("mma.sync.aligned.m16n8k16.row.col.f32.bf16.bf16.f32 " \
        "{%0,%1,%2,%3}, {%4,%5,%6,%7}, {%8,%9}, {%0,%1,%2,%3};" \
        : "+f"((d)[0]), "+f"((d)[1]), "+f"((d)[2]), "+f"((d)[3]) \
        : "r"((a)[0]), "r"((a)[1]), "r"((a)[2]), "r"((a)[3]), \
          "r"(b0v), "r"(b1v))

// ---------------- init + counts ---------------------------------------------
__global__ void k_zero() {
    int i = blockIdx.x * blockDim.x + threadIdx.x;
    if (i < NN) g_deg[i] = 0;
    if (i < NG) g_gcnt[i] = 0;
}

__global__ void k_count(const int* __restrict__ ei, const int* __restrict__ batch) {
    int e = blockIdx.x * blockDim.x + threadIdx.x;
    if (e < NE) atomicAdd(&g_deg[ei[NE + e]], 1);
    if (e < NN) atomicAdd(&g_gcnt[batch[e]], 1);
}

// ---------------- hierarchical scan of degrees ------------------------------
__global__ void k_blocksum() {
    __shared__ int wsum[8];
    int i = blockIdx.x * SCAN_B + threadIdx.x;
    int v = (i < NN) ? g_deg[i] : 0;
    int s = v;
#pragma unroll
    for (int o = 16; o > 0; o >>= 1) s += __shfl_down_sync(0xffffffffu, s, o);
    if ((threadIdx.x & 31) == 0) wsum[threadIdx.x >> 5] = s;
    __syncthreads();
    if (threadIdx.x == 0) {
        int t = 0;
#pragma unroll
        for (int w = 0; w < 8; w++) t += wsum[w];
        g_bsum[blockIdx.x] = t;
    }
}

__global__ void k_scan2() {
    __shared__ int sh[SCAN_B];
    int t = threadIdx.x;
    sh[t] = (t < NBLK) ? g_bsum[t] : 0;
    __syncthreads();
#pragma unroll
    for (int off = 1; off < SCAN_B; off <<= 1) {
        int v = (t >= off) ? sh[t - off] : 0;
        __syncthreads();
        sh[t] += v;
        __syncthreads();
    }
    if (t < NBLK) g_boff[t] = (t > 0) ? sh[t - 1] : 0;
}

__global__ void k_apply() {
    __shared__ int wsum[8];
    int lane = threadIdx.x & 31;
    int wid  = threadIdx.x >> 5;
    int i = blockIdx.x * SCAN_B + threadIdx.x;
    int v = (i < NN) ? g_deg[i] : 0;
    int inc = v;
#pragma unroll
    for (int o = 1; o < 32; o <<= 1) {
        int u = __shfl_up_sync(0xffffffffu, inc, o);
        if (lane >= o) inc += u;
    }
    if (lane == 31) wsum[wid] = inc;
    __syncthreads();
    if (wid == 0) {
        int ws = (lane < 8) ? wsum[lane] : 0;
#pragma unroll
        for (int o = 1; o < 8; o <<= 1) {
            int u = __shfl_up_sync(0xffffffffu, ws, o);
            if (lane >= o) ws += u;
        }
        if (lane < 8) wsum[lane] = ws;
    }
    __syncthreads();
    int excl = inc - v + ((wid > 0) ? wsum[wid - 1] : 0) + g_boff[blockIdx.x];
    if (i < NN) {
        g_rowstart[i] = excl;
        g_cursor[i]   = excl;
        g_invdeg[i]   = (v > 0) ? 1.0f / (float)v : 0.0f;
    }
}

__global__ void k_fill(const int* __restrict__ ei) {
    int e = blockIdx.x * blockDim.x + threadIdx.x;
    if (e >= NE) return;
    int s = ei[e];
    int d = ei[NE + e];
    int pos = atomicAdd(&g_cursor[d], 1);
    g_csr[pos] = s;
}

// ---------------- bf16 conversion kernels -----------------------------------
__global__ void k_cvtX(const float* __restrict__ x) {
    int i = blockIdx.x * blockDim.x + threadIdx.x;
    if (i < NN * DIM) {
        uint16_t h, l;
        bf16_split(x[i], h, l);
        g_xh[i] = h; g_xl[i] = l;
    }
}

__global__ void k_cvtW(const float* __restrict__ w, int off) {
    int i = blockIdx.x * blockDim.x + threadIdx.x;
    if (i < 16384) {
        uint16_t h, l;
        bf16_split(w[i], h, l);
        g_Wbh[off + i] = h; g_Wbl[off + i] = l;
    }
}

// ---------------- mean aggregation (warp per node) --------------------------
__global__ void k_agg(const float* __restrict__ x, int sel) {
    const float* hin = (sel == 0) ? x : ((sel == 1) ? g_hA : g_hB);
    int gw   = (blockIdx.x * blockDim.x + threadIdx.x) >> 5;
    int lane = threadIdx.x & 31;
    if (gw >= NN) return;
    int start = g_rowstart[gw];
    int d     = g_deg[gw];
    const float4* x4 = (const float4*)hin;
    float a0 = 0.f, a1 = 0.f, a2 = 0.f, a3 = 0.f;
    int j = 0;
    for (; j + 4 <= d; j += 4) {
        int s0 = g_csr[start + j + 0];
        int s1 = g_csr[start + j + 1];
        int s2 = g_csr[start + j + 2];
        int s3 = g_csr[start + j + 3];
        float4 v0 = x4[s0 * 32 + lane];
        float4 v1 = x4[s1 * 32 + lane];
        float4 v2 = x4[s2 * 32 + lane];
        float4 v3 = x4[s3 * 32 + lane];
        a0 += v0.x + v1.x + v2.x + v3.x;
        a1 += v0.y + v1.y + v2.y + v3.y;
        a2 += v0.z + v1.z + v2.z + v3.z;
        a3 += v0.w + v1.w + v2.w + v3.w;
    }
    for (; j < d; j++) {
        int s0 = g_csr[start + j];
        float4 v = x4[s0 * 32 + lane];
        a0 += v.x; a1 += v.y; a2 += v.z; a3 += v.w;
    }
    float inv = g_invdeg[gw];
    a0 *= inv; a1 *= inv; a2 *= inv; a3 *= inv;
    uint16_t h0, l0, h1, l1, h2, l2, h3, l3;
    bf16_split(a0, h0, l0); bf16_split(a1, h1, l1);
    bf16_split(a2, h2, l2); bf16_split(a3, h3, l3);
    int idx = gw * 128 + lane * 4;
    uint2 ph = make_uint2((uint32_t)h0 | ((uint32_t)h1 << 16),
                          (uint32_t)h2 | ((uint32_t)h3 << 16));
    uint2 pl = make_uint2((uint32_t)l0 | ((uint32_t)l1 << 16),
                          (uint32_t)l2 | ((uint32_t)l3 << 16));
    *(uint2*)&g_aggh[idx] = ph;
    *(uint2*)&g_aggl[idx] = pl;
}

// ---------------- bf16-split tensor GEMM ------------------------------------
// layer selector resolves ALL device-global pointers in device code.
#define AST 40   // smem row stride in bf16 elems (80B -> conflict-free ldmatrix)

__global__ void __launch_bounds__(256, 2) k_gemm_mma(
    int layer, const float* __restrict__ bl)
{
    const uint16_t* rsh;
    const uint16_t* rsl;
    float*    hout;
    uint16_t* outh;
    uint16_t* outl;
    int woff, relu, emit;
    if (layer == 0) {
        rsh = g_xh;  rsl = g_xl;  woff = 0;
        hout = g_hA; outh = g_hh0; outl = g_hl0; relu = 1; emit = 1;
    } else if (layer == 1) {
        rsh = g_hh0; rsl = g_hl0; woff = 32768;
        hout = g_hB; outh = g_hh1; outl = g_hl1; relu = 1; emit = 1;
    } else {
        rsh = g_hh1; rsl = g_hl1; woff = 65536;
        hout = g_hA; outh = nullptr; outl = nullptr; relu = 0; emit = 0;
    }

    __shared__ uint16_t sAh[128 * AST];
    __shared__ uint16_t sAl[128 * AST];
    __shared__ uint16_t sBh[128 * AST];
    __shared__ uint16_t sBl[128 * AST];
    __shared__ float bias_s[128];

    int tid  = threadIdx.x;
    int wid  = tid >> 5;
    int lane = tid & 31;
    int nb   = blockIdx.x * 128;
    int m0   = (wid & 3) * 32;
    int n0   = (wid >> 2) * 64;

    if (tid < 128) bias_s[tid] = bl[tid];

    float acc[2][8][4];
#pragma unroll
    for (int i = 0; i < 2; i++)
#pragma unroll
        for (int j = 0; j < 8; j++)
#pragma unroll
            for (int q = 0; q < 4; q++) acc[i][j][q] = 0.f;

    for (int chunk = 0; chunk < 8; chunk++) {
        int kk0 = (chunk & 3) * 32;
        const uint16_t* pAh = (chunk < 4) ? g_aggh : rsh;
        const uint16_t* pAl = (chunk < 4) ? g_aggl : rsl;
        const uint16_t* pBh = g_Wbh + woff + ((chunk < 4) ? 0 : 16384);
        const uint16_t* pBl = g_Wbl + woff + ((chunk < 4) ? 0 : 16384);

        __syncthreads();
#pragma unroll
        for (int r = 0; r < 2; r++) {
            int c   = tid + r * 256;    // 0..511
            int row = c >> 2;
            int seg = c & 3;
            int node = nb + row;
            uint4 vh = make_uint4(0, 0, 0, 0), vl = make_uint4(0, 0, 0, 0);
            if (node < NN) {
                vh = *(const uint4*)&pAh[node * 128 + kk0 + seg * 8];
                vl = *(const uint4*)&pAl[node * 128 + kk0 + seg * 8];
            }
            *(uint4*)&sAh[row * AST + seg * 8] = vh;
            *(uint4*)&sAl[row * AST + seg * 8] = vl;
            uint4 wh = *(const uint4*)&pBh[row * 128 + kk0 + seg * 8];
            uint4 wl = *(const uint4*)&pBl[row * 128 + kk0 + seg * 8];
            *(uint4*)&sBh[row * AST + seg * 8] = wh;
            *(uint4*)&sBl[row * AST + seg * 8] = wl;
        }
        __syncthreads();

#pragma unroll
        for (int ks = 0; ks < 32; ks += 16) {
            uint32_t ah[2][4], alr[2][4], bh[4][4], blr[4][4];
#pragma unroll
            for (int mt = 0; mt < 2; mt++) {
                int row = m0 + mt * 16 + (lane & 15);
                int col = ks + (lane >> 4) * 8;
                LDSM_X4(ah[mt],  smem_u32(&sAh[row * AST + col]));
                LDSM_X4(alr[mt], smem_u32(&sAl[row * AST + col]));
            }
#pragma unroll
            for (int bt = 0; bt < 4; bt++) {
                int row = n0 + bt * 16 + (lane & 7) + ((lane >> 4) & 1) * 8;
                int col = ks + ((lane >> 3) & 1) * 8;
                LDSM_X4(bh[bt],  smem_u32(&sBh[row * AST + col]));
                LDSM_X4(blr[bt], smem_u32(&sBl[row * AST + col]));
            }
#pragma unroll
            for (int mt = 0; mt < 2; mt++)
#pragma unroll
                for (int nt = 0; nt < 8; nt++) {
                    int bg = nt >> 1, pr = (nt & 1) * 2;
                    MMA_BF16(acc[mt][nt], ah[mt],  bh[bg][pr],  bh[bg][pr + 1]);
                    MMA_BF16(acc[mt][nt], alr[mt], bh[bg][pr],  bh[bg][pr + 1]);
                    MMA_BF16(acc[mt][nt], ah[mt],  blr[bg][pr], blr[bg][pr + 1]);
                }
        }
    }

    // ---- epilogue ----
    int g  = lane >> 2;
    int tg = lane & 3;
#pragma unroll
    for (int mt = 0; mt < 2; mt++)
#pragma unroll
        for (int nt = 0; nt < 8; nt++) {
            int colb = n0 + nt * 8 + tg * 2;
            float b0 = bias_s[colb], b1 = bias_s[colb + 1];
#pragma unroll
            for (int half = 0; half < 2; half++) {
                int row = nb + m0 + mt * 16 + g + half * 8;
                if (row >= NN) continue;
                float v0 = acc[mt][nt][half * 2 + 0] + b0;
                float v1 = acc[mt][nt][half * 2 + 1] + b1;
                if (relu) { v0 = fmaxf(v0, 0.f); v1 = fmaxf(v1, 0.f); }
                *(float2*)&hout[row * 128 + colb] = make_float2(v0, v1);
                if (emit) {
                    uint16_t h0, l0, h1, l1;
                    bf16_split(v0, h0, l0);
                    bf16_split(v1, h1, l1);
                    *(uint32_t*)&outh[row * 128 + colb] =
                        (uint32_t)h0 | ((uint32_t)h1 << 16);
                    *(uint32_t*)&outl[row * 128 + colb] =
                        (uint32_t)l0 | ((uint32_t)l1 << 16);
                }
            }
        }
}

// ---------------- global mean pool ------------------------------------------
__global__ void k_pool(float* __restrict__ out) {
    int g = blockIdx.x;
    int c = threadIdx.x;
    int start = 0;
    for (int i = 0; i < g; i++) start += g_gcnt[i];
    int cnt = g_gcnt[g];
    float s = 0.f;
    for (int r = 0; r < cnt; r++)
        s += g_hA[(start + r) * 128 + c];
    out[g * 128 + c] = (cnt > 0) ? s / (float)cnt : 0.0f;
}

// ---------------- launch ----------------------------------------------------
extern "C" void kernel_launch(void* const* d_in, const int* in_sizes, int n_in,
                              void* d_out, int out_size)
{
    const float* x     = (const float*)d_in[0];
    const int*   ei    = (const int*)d_in[1];
    const int*   batch = (const int*)d_in[2];
    const float* Wl0 = (const float*)d_in[3];
    const float* bl0 = (const float*)d_in[4];
    const float* Wr0 = (const float*)d_in[5];
    const float* Wl1 = (const float*)d_in[6];
    const float* bl1 = (const float*)d_in[7];
    const float* Wr1 = (const float*)d_in[8];
    const float* Wl2 = (const float*)d_in[9];
    const float* bl2 = (const float*)d_in[10];
    const float* Wr2 = (const float*)d_in[11];
    float* out = (float*)d_out;

    // CSR build
    k_zero<<<(NN + 255) / 256, 256>>>();
    k_count<<<(NE + 255) / 256, 256>>>(ei, batch);
    k_blocksum<<<NBLK, SCAN_B>>>();
    k_scan2<<<1, SCAN_B>>>();
    k_apply<<<NBLK, SCAN_B>>>();
    k_fill<<<(NE + 255) / 256, 256>>>(ei);

    // one-time conversions
    k_cvtX<<<(NN * DIM + 255) / 256, 256>>>(x);
    k_cvtW<<<64, 256>>>(Wl0, 0);
    k_cvtW<<<64, 256>>>(Wr0, 16384);
    k_cvtW<<<64, 256>>>(Wl1, 32768);
    k_cvtW<<<64, 256>>>(Wr1, 49152);
    k_cvtW<<<64, 256>>>(Wl2, 65536);
    k_cvtW<<<64, 256>>>(Wr2, 81920);

    int agg_blocks  = (NN * 32 + 255) / 256;
    int gemm_blocks = (NN + 127) / 128;   // 391

    // layer 0
    k_agg<<<agg_blocks, 256>>>(x, 0);
    k_gemm_mma<<<gemm_blocks, 256>>>(0, bl0);
    // layer 1
    k_agg<<<agg_blocks, 256>>>(x, 1);
    k_gemm_mma<<<gemm_blocks, 256>>>(1, bl1);
    // layer 2
    k_agg<<<agg_blocks, 256>>>(x, 2);
    k_gemm_mma<<<gemm_blocks, 256>>>(2, bl2);
    // pool
    k_pool<<<NG, 128>>>(out);
}